// round 6
// baseline (speedup 1.0000x reference)
#include <cuda_runtime.h>

#define TM      16
#define NTH     512
#define DSTATE  256
#define DIN     512
#define NW      512
#define NSTEPS  60
#define NBLOCKS 128

typedef unsigned long long u64;

__constant__ float c_A[6][5] = {
    {0.f, 0.f, 0.f, 0.f, 0.f},
    {0.161f, 0.f, 0.f, 0.f, 0.f},
    {-0.008480655492356989f, 0.335480655492357f, 0.f, 0.f, 0.f},
    {2.8971530571054935f, -6.359448489975075f, 4.3622954328695815f, 0.f, 0.f},
    {5.325864828439257f, -11.748883564062828f, 7.4955393428898365f, -0.09249506636175525f, 0.f},
    {5.86145544294642f, -12.92096931784711f, 8.159367898576159f, -0.071584973281401f, -0.028269050394068383f}};
__constant__ float c_Bw[6] = {
    0.09646076681806523f, 0.01f, 0.4798896504144996f,
    1.379008574103742f, -3.290069515436081f, 2.324710524099774f};

// +2 rows pad: weight prefetch overreads 2 k-rows at the loop tail (discarded).
__device__ float g_W1T[(DIN + 2) * NW];
__device__ float g_W2T[(NW + 2) * NW];
__device__ float g_W3T[(NW + 2) * DSTATE];
__device__ float g_BU[NBLOCKS * NW * TM];            // b1 + W1[:,256:]@u per CTA
__device__ float g_KB[NBLOCKS * 6 * DSTATE * TM];    // stage derivatives (L2-resident)

// ---------------- packed f32x2 helpers ----------------
static __device__ __forceinline__ u64 pk2(float x, float y) {
    u64 d; asm("mov.b64 %0, {%1, %2};" : "=l"(d) : "f"(x), "f"(y)); return d;
}
static __device__ __forceinline__ u64 fma2(u64 a, u64 b, u64 c) {
    u64 d; asm("fma.rn.f32x2 %0, %1, %2, %3;" : "=l"(d) : "l"(a), "l"(b), "l"(c)); return d;
}

// ---------------- weight transpose: src[N][K] -> dst[K][N] ----------------
__global__ void transpose_kernel(int which, const float* __restrict__ src, int N, int K) {
    float* dst = (which == 0) ? g_W1T : (which == 1) ? g_W2T : g_W3T;
    __shared__ float tile[32][33];
    int kb = blockIdx.x * 32, nb = blockIdx.y * 32;
    int tx = threadIdx.x, ty = threadIdx.y;
    #pragma unroll
    for (int i = ty; i < 32; i += 8) tile[i][tx] = src[(nb + i) * K + (kb + tx)];
    __syncthreads();
    #pragma unroll
    for (int i = ty; i < 32; i += 8) dst[(kb + i) * N + (nb + tx)] = tile[tx][i];
}

// ---------------- 8m x 8n register-tile GEMM, weights prefetched 1 iter ahead ----
struct W8 { float4 a, b; };

static __device__ __forceinline__ W8 ldw8(const float* __restrict__ Wg, int ldw, int k) {
    W8 w;
    const float* r = Wg + (size_t)k * ldw;
    w.a = *reinterpret_cast<const float4*>(r);
    w.b = *reinterpret_cast<const float4*>(r + 4);
    return w;
}

static __device__ __forceinline__ void cmp8(const ulonglong2& aa, const ulonglong2& ab,
                                            const W8& w, u64* __restrict__ acc) {
    float wv[8] = {w.a.x, w.a.y, w.a.z, w.a.w, w.b.x, w.b.y, w.b.z, w.b.w};
    #pragma unroll
    for (int nj = 0; nj < 8; ++nj) {
        u64 wd = pk2(wv[nj], wv[nj]);
        acc[nj * 4 + 0] = fma2(aa.x, wd, acc[nj * 4 + 0]);
        acc[nj * 4 + 1] = fma2(aa.y, wd, acc[nj * 4 + 1]);
        acc[nj * 4 + 2] = fma2(ab.x, wd, acc[nj * 4 + 2]);
        acc[nj * 4 + 3] = fma2(ab.y, wd, acc[nj * 4 + 3]);
    }
}

// KH multiple of 2. Weight prefetch overreads rows KH..KH+1 (padded / next slice).
// Activations read strictly within [0, KH) rows of Asm.
static __device__ __forceinline__ void mma8x8(
    const float* __restrict__ Asm, const float* __restrict__ Wg,
    int ldw, int KH, u64* __restrict__ acc) {
    W8 w0 = ldw8(Wg, ldw, 0);
    W8 w1 = ldw8(Wg, ldw, 1);
    #pragma unroll 1
    for (int k = 0; k < KH; k += 2) {
        W8 nw0 = ldw8(Wg, ldw, k + 2);
        W8 nw1 = ldw8(Wg, ldw, k + 3);
        ulonglong2 a0 = *reinterpret_cast<const ulonglong2*>(Asm + k * TM);
        ulonglong2 b0 = *reinterpret_cast<const ulonglong2*>(Asm + k * TM + 4);
        ulonglong2 a1 = *reinterpret_cast<const ulonglong2*>(Asm + (k + 1) * TM);
        ulonglong2 b1 = *reinterpret_cast<const ulonglong2*>(Asm + (k + 1) * TM + 4);
        cmp8(a0, b0, w0, acc);
        cmp8(a1, b1, w1, acc);
        w0 = nw0; w1 = nw1;
    }
}

static __device__ __forceinline__ void store_partial(
    float* __restrict__ dst, int n0, int m0, const u64* __restrict__ acc) {
    #pragma unroll
    for (int nj = 0; nj < 8; ++nj) {
        ulonglong2 v, w;
        v.x = acc[nj * 4 + 0]; v.y = acc[nj * 4 + 1];
        w.x = acc[nj * 4 + 2]; w.y = acc[nj * 4 + 3];
        *reinterpret_cast<ulonglong2*>(dst + (n0 + nj) * TM + m0) = v;
        *reinterpret_cast<ulonglong2*>(dst + (n0 + nj) * TM + m0 + 4) = w;
    }
}

static __device__ __forceinline__ void zero_acc(u64* acc) {
    #pragma unroll
    for (int i = 0; i < 32; ++i) acc[i] = 0ull;
}

// ---------------- main fused Tsit5 kernel ----------------
__global__ void __launch_bounds__(NTH, 1)
ode_main(const float* __restrict__ x0, const float* __restrict__ uf,
         const float* __restrict__ b1, const float* __restrict__ b2,
         const float* __restrict__ b3, float* __restrict__ out) {
    extern __shared__ float smem[];
    float* A0 = smem;                 // [512][16] z (rows 0-255) / gemm2 output
    float* A1 = A0 + NW * TM;         // [512][16] gemm1 output
    float* P1 = A1 + NW * TM;         // [512][16] partials
    float* P2 = P1 + NW * TM;
    float* P3 = P2 + NW * TM;
    float* Y  = P3 + NW * TM;         // [256][16]

    const int tid = threadIdx.x;
    const int r0 = blockIdx.x * TM;
    float* BUg = g_BU + (size_t)blockIdx.x * (NW * TM);
    float* gKB = g_KB + (size_t)blockIdx.x * (6 * DSTATE * TM);

    // N=512 gemms: 4-way k-split, 128 positions (2m x 64n)
    const int q4 = tid >> 7;
    const int pos4 = tid & 127;
    const int m4 = (pos4 & 1) * 8;
    const int n4 = (pos4 >> 1) * 8;
    // N=256 gemm: 8-way k-split, 64 positions (2m x 32n)
    const int q8 = tid >> 6;
    const int pos8 = tid & 63;
    const int m8 = (pos8 & 1) * 8;
    const int n8 = (pos8 >> 1) * 8;

    float* const part4[4] = {A1, P1, P2, P3};
    float* const part8[8] = {A1, A1 + DSTATE * TM, P1, P1 + DSTATE * TM,
                             P2, P2 + DSTATE * TM, P3, P3 + DSTATE * TM};

    // init Y; u into A0 rows 0-255 (k-major) for BU precompute
    for (int idx = tid; idx < TM * DSTATE; idx += NTH) {
        int m = idx >> 8, c = idx & 255;
        int r = r0 + m, traj = r & 1023;
        Y[c * TM + m] = x0[traj * DSTATE + c];
        A0[c * TM + m] = (r < 1024) ? uf[traj * DSTATE + c] : 0.f;
    }
    __syncthreads();

    // ---- BU = b1 + W1[:,256:512] @ u ----
    {
        u64 acc[32];
        zero_acc(acc);
        mma8x8(A0 + q4 * 64 * TM + m4,
               g_W1T + (size_t)(DSTATE + q4 * 64) * NW + n4, NW, 64, acc);
        store_partial(part4[q4], n4, m4, acc);
        __syncthreads();
        for (int i4 = tid; i4 < (NW * TM) / 4; i4 += NTH) {
            float4 a = reinterpret_cast<const float4*>(A1)[i4];
            float4 p = reinterpret_cast<const float4*>(P1)[i4];
            float4 r2 = reinterpret_cast<const float4*>(P2)[i4];
            float4 r3 = reinterpret_cast<const float4*>(P3)[i4];
            float bb = b1[i4 >> 2];
            reinterpret_cast<float4*>(BUg)[i4] = make_float4(
                a.x + p.x + r2.x + r3.x + bb, a.y + p.y + r2.y + r3.y + bb,
                a.z + p.z + r2.z + r3.z + bb, a.w + p.w + r2.w + r3.w + bb);
        }
        __syncthreads();
    }

    const float H = 1.0f / 60.0f;

    #pragma unroll 1
    for (int step = 0; step < NSTEPS; ++step) {
        #pragma unroll 1
        for (int s = 0; s < 6; ++s) {
            // build z = y + H * sum_j a_sj k_j -> A0 rows [0,256)
            for (int i4 = tid; i4 < (DSTATE * TM) / 4; i4 += NTH) {
                float4 y = reinterpret_cast<const float4*>(Y)[i4];
                float4 a = make_float4(0.f, 0.f, 0.f, 0.f);
                for (int j = 0; j < s; ++j) {
                    float4 kv = reinterpret_cast<const float4*>(gKB + j * DSTATE * TM)[i4];
                    float aj = c_A[s][j];
                    a.x += aj * kv.x; a.y += aj * kv.y;
                    a.z += aj * kv.z; a.w += aj * kv.w;
                }
                y.x += H * a.x; y.y += H * a.y; y.z += H * a.z; y.w += H * a.w;
                reinterpret_cast<float4*>(A0)[i4] = y;
            }
            __syncthreads();

            // gemm1: A1 = relu(BU + W1[:, :256] @ z), K=256, 4-way split
            {
                u64 acc[32];
                zero_acc(acc);
                mma8x8(A0 + q4 * 64 * TM + m4,
                       g_W1T + (size_t)(q4 * 64) * NW + n4, NW, 64, acc);
                store_partial(part4[q4], n4, m4, acc);
                __syncthreads();
                for (int i4 = tid; i4 < (NW * TM) / 4; i4 += NTH) {
                    float4 a = reinterpret_cast<const float4*>(A1)[i4];
                    float4 p = reinterpret_cast<const float4*>(P1)[i4];
                    float4 r2 = reinterpret_cast<const float4*>(P2)[i4];
                    float4 r3 = reinterpret_cast<const float4*>(P3)[i4];
                    float4 bu = reinterpret_cast<const float4*>(BUg)[i4];
                    float4 v;
                    v.x = fmaxf(a.x + p.x + r2.x + r3.x + bu.x, 0.f);
                    v.y = fmaxf(a.y + p.y + r2.y + r3.y + bu.y, 0.f);
                    v.z = fmaxf(a.z + p.z + r2.z + r3.z + bu.z, 0.f);
                    v.w = fmaxf(a.w + p.w + r2.w + r3.w + bu.w, 0.f);
                    reinterpret_cast<float4*>(A1)[i4] = v;
                }
                __syncthreads();
            }
            // gemm2: A0 = relu(b2 + W2 @ h1), K=512, 4-way split
            {
                u64 acc[32];
                zero_acc(acc);
                mma8x8(A1 + q4 * 128 * TM + m4,
                       g_W2T + (size_t)(q4 * 128) * NW + n4, NW, 128, acc);
                store_partial(q4 == 0 ? A0 : part4[q4], n4, m4, acc);
                __syncthreads();
                for (int i4 = tid; i4 < (NW * TM) / 4; i4 += NTH) {
                    float4 a = reinterpret_cast<const float4*>(A0)[i4];
                    float4 p = reinterpret_cast<const float4*>(P1)[i4];
                    float4 r2 = reinterpret_cast<const float4*>(P2)[i4];
                    float4 r3 = reinterpret_cast<const float4*>(P3)[i4];
                    float bb = b2[i4 >> 2];
                    float4 v;
                    v.x = fmaxf(a.x + p.x + r2.x + r3.x + bb, 0.f);
                    v.y = fmaxf(a.y + p.y + r2.y + r3.y + bb, 0.f);
                    v.z = fmaxf(a.z + p.z + r2.z + r3.z + bb, 0.f);
                    v.w = fmaxf(a.w + p.w + r2.w + r3.w + bb, 0.f);
                    reinterpret_cast<float4*>(A0)[i4] = v;
                }
                __syncthreads();
            }
            // gemm3: k_s = b3 + W3 @ h2, K=512, N=256, 8-way split
            {
                u64 acc[32];
                zero_acc(acc);
                mma8x8(A0 + q8 * 64 * TM + m8,
                       g_W3T + (size_t)(q8 * 64) * DSTATE + n8, DSTATE, 64, acc);
                store_partial(part8[q8], n8, m8, acc);
                __syncthreads();
                float* gKBs = gKB + s * DSTATE * TM;
                for (int i4 = tid; i4 < (DSTATE * TM) / 4; i4 += NTH) {
                    float4 v = make_float4(b3[i4 >> 2], b3[i4 >> 2], b3[i4 >> 2], b3[i4 >> 2]);
                    #pragma unroll
                    for (int o = 0; o < 8; ++o) {
                        float4 p = reinterpret_cast<const float4*>(part8[o])[i4];
                        v.x += p.x; v.y += p.y; v.z += p.z; v.w += p.w;
                    }
                    reinterpret_cast<float4*>(gKBs)[i4] = v;
                }
                __syncthreads();
            }
        }
        // y += H * sum_i b_i k_i
        for (int i4 = tid; i4 < (DSTATE * TM) / 4; i4 += NTH) {
            float4 y = reinterpret_cast<const float4*>(Y)[i4];
            float4 a = make_float4(0.f, 0.f, 0.f, 0.f);
            #pragma unroll
            for (int j = 0; j < 6; ++j) {
                float4 kv = reinterpret_cast<const float4*>(gKB + j * DSTATE * TM)[i4];
                float bj = c_Bw[j];
                a.x += bj * kv.x; a.y += bj * kv.y;
                a.z += bj * kv.z; a.w += bj * kv.w;
            }
            y.x += H * a.x; y.y += H * a.y; y.z += H * a.z; y.w += H * a.w;
            reinterpret_cast<float4*>(Y)[i4] = y;
        }
        __syncthreads();
    }

    for (int idx = tid; idx < TM * DSTATE; idx += NTH) {
        int m = idx >> 8, c = idx & 255;
        out[(size_t)(r0 + m) * DSTATE + c] = Y[c * TM + m];
    }
}

// ---------------- launch ----------------
extern "C" void kernel_launch(void* const* d_in, const int* in_sizes, int n_in,
                              void* d_out, int out_size) {
    (void)in_sizes; (void)n_in; (void)out_size;
    const float* x0 = (const float*)d_in[0];
    const float* uf = (const float*)d_in[1];
    const float* W1 = (const float*)d_in[2];
    const float* b1 = (const float*)d_in[3];
    const float* W2 = (const float*)d_in[4];
    const float* b2 = (const float*)d_in[5];
    const float* W3 = (const float*)d_in[6];
    const float* b3 = (const float*)d_in[7];
    float* out = (float*)d_out;

    dim3 tthreads(32, 8);
    transpose_kernel<<<dim3(DIN / 32, NW / 32), tthreads>>>(0, W1, NW, DIN);
    transpose_kernel<<<dim3(NW / 32, NW / 32), tthreads>>>(1, W2, NW, NW);
    transpose_kernel<<<dim3(NW / 32, DSTATE / 32), tthreads>>>(2, W3, DSTATE, NW);

    size_t smem_bytes = (size_t)(5 * NW * TM + DSTATE * TM) * sizeof(float);
    cudaFuncSetAttribute(ode_main, cudaFuncAttributeMaxDynamicSharedMemorySize, (int)smem_bytes);
    ode_main<<<NBLOCKS, NTH, smem_bytes>>>(x0, uf, b1, b2, b3, out);
}

// round 7
// speedup vs baseline: 1.1082x; 1.1082x over previous
#include <cuda_runtime.h>

#define TM      16
#define NTH     512
#define DSTATE  256
#define DIN     512
#define NW      512
#define NSTEPS  60
#define NBLOCKS 128

typedef unsigned long long u64;

__constant__ float c_A[6][5] = {
    {0.f, 0.f, 0.f, 0.f, 0.f},
    {0.161f, 0.f, 0.f, 0.f, 0.f},
    {-0.008480655492356989f, 0.335480655492357f, 0.f, 0.f, 0.f},
    {2.8971530571054935f, -6.359448489975075f, 4.3622954328695815f, 0.f, 0.f},
    {5.325864828439257f, -11.748883564062828f, 7.4955393428898365f, -0.09249506636175525f, 0.f},
    {5.86145544294642f, -12.92096931784711f, 8.159367898576159f, -0.071584973281401f, -0.028269050394068383f}};
__constant__ float c_Bw[6] = {
    0.09646076681806523f, 0.01f, 0.4798896504144996f,
    1.379008574103742f, -3.290069515436081f, 2.324710524099774f};

// +4 rows pad: weight prefetch overreads up to 4 k-rows at the loop tail.
__device__ float g_W1T[(DIN + 4) * NW];
__device__ float g_W2T[(NW + 4) * NW];
__device__ float g_W3T[(NW + 4) * DSTATE];
__device__ float g_BU[NBLOCKS * NW * TM];   // per-CTA b1 + W1[:,256:]@u

// ---------------- packed f32x2 helpers ----------------
static __device__ __forceinline__ u64 pk2(float x, float y) {
    u64 d; asm("mov.b64 %0, {%1, %2};" : "=l"(d) : "f"(x), "f"(y)); return d;
}
static __device__ __forceinline__ u64 fma2(u64 a, u64 b, u64 c) {
    u64 d; asm("fma.rn.f32x2 %0, %1, %2, %3;" : "=l"(d) : "l"(a), "l"(b), "l"(c)); return d;
}

// ---------------- weight transpose: src[N][K] -> dst[K][N] ----------------
__global__ void transpose_kernel(int which, const float* __restrict__ src, int N, int K) {
    float* dst = (which == 0) ? g_W1T : (which == 1) ? g_W2T : g_W3T;
    __shared__ float tile[32][33];
    int kb = blockIdx.x * 32, nb = blockIdx.y * 32;
    int tx = threadIdx.x, ty = threadIdx.y;
    #pragma unroll
    for (int i = ty; i < 32; i += 8) tile[i][tx] = src[(nb + i) * K + (kb + tx)];
    __syncthreads();
    #pragma unroll
    for (int i = ty; i < 32; i += 8) dst[(kb + i) * N + (nb + tx)] = tile[tx][i];
}

// ---------------- 8m x 4n register-tile GEMM (acc = 16 u64 = 32 floats) -----
// Asm pre-offset to (k0*TM + m0): per k reads 8 m floats (2x LDS.128, JIT).
// Wg pre-offset to (k0*ldw + n0): per k reads 4 n floats (1x LDG.128),
// prefetched 4 k ahead to cover L2 latency.
static __device__ __forceinline__ void cmpk(const float* __restrict__ Asm, int k,
                                            const float4& w, u64* __restrict__ acc) {
    ulonglong2 a0 = *reinterpret_cast<const ulonglong2*>(Asm + k * TM);
    ulonglong2 a1 = *reinterpret_cast<const ulonglong2*>(Asm + k * TM + 4);
    u64 w0 = pk2(w.x, w.x), w1 = pk2(w.y, w.y), w2 = pk2(w.z, w.z), w3 = pk2(w.w, w.w);
    acc[0]  = fma2(a0.x, w0, acc[0]);  acc[1]  = fma2(a0.y, w0, acc[1]);
    acc[2]  = fma2(a1.x, w0, acc[2]);  acc[3]  = fma2(a1.y, w0, acc[3]);
    acc[4]  = fma2(a0.x, w1, acc[4]);  acc[5]  = fma2(a0.y, w1, acc[5]);
    acc[6]  = fma2(a1.x, w1, acc[6]);  acc[7]  = fma2(a1.y, w1, acc[7]);
    acc[8]  = fma2(a0.x, w2, acc[8]);  acc[9]  = fma2(a0.y, w2, acc[9]);
    acc[10] = fma2(a1.x, w2, acc[10]); acc[11] = fma2(a1.y, w2, acc[11]);
    acc[12] = fma2(a0.x, w3, acc[12]); acc[13] = fma2(a0.y, w3, acc[13]);
    acc[14] = fma2(a1.x, w3, acc[14]); acc[15] = fma2(a1.y, w3, acc[15]);
}

// KH multiple of 4. Weight prefetch overreads rows KH..KH+3 (padded arrays).
static __device__ __forceinline__ void mma8x4(
    const float* __restrict__ Asm, const float* __restrict__ Wg,
    int ldw, int KH, u64* __restrict__ acc) {
    float4 w0 = *reinterpret_cast<const float4*>(Wg);
    float4 w1 = *reinterpret_cast<const float4*>(Wg + (size_t)ldw);
    #pragma unroll 1
    for (int k = 0; k < KH; k += 4) {
        float4 c0 = *reinterpret_cast<const float4*>(Wg + (size_t)(k + 2) * ldw);
        float4 c1 = *reinterpret_cast<const float4*>(Wg + (size_t)(k + 3) * ldw);
        cmpk(Asm, k, w0, acc);
        cmpk(Asm, k + 1, w1, acc);
        w0 = *reinterpret_cast<const float4*>(Wg + (size_t)(k + 4) * ldw);  // tail overread
        w1 = *reinterpret_cast<const float4*>(Wg + (size_t)(k + 5) * ldw);
        cmpk(Asm, k + 2, c0, acc);
        cmpk(Asm, k + 3, c1, acc);
    }
}

static __device__ __forceinline__ void store_partial4(
    float* __restrict__ dst, int n0, int m0, const u64* __restrict__ acc) {
    #pragma unroll
    for (int nj = 0; nj < 4; ++nj) {
        ulonglong2 v, w;
        v.x = acc[nj * 4 + 0]; v.y = acc[nj * 4 + 1];
        w.x = acc[nj * 4 + 2]; w.y = acc[nj * 4 + 3];
        *reinterpret_cast<ulonglong2*>(dst + (n0 + nj) * TM + m0) = v;
        *reinterpret_cast<ulonglong2*>(dst + (n0 + nj) * TM + m0 + 4) = w;
    }
}

static __device__ __forceinline__ void zero16(u64* acc) {
    #pragma unroll
    for (int i = 0; i < 16; ++i) acc[i] = 0ull;
}

// ---------------- main fused Tsit5 kernel ----------------
__global__ void __launch_bounds__(NTH, 1)
ode_main(const float* __restrict__ x0, const float* __restrict__ uf,
         const float* __restrict__ b1, const float* __restrict__ b2,
         const float* __restrict__ b3, float* __restrict__ out) {
    extern __shared__ float smem[];
    float* A0 = smem;                 // [512][16] z (rows 0-255) / gemm2 out+partial0
    float* A1 = A0 + NW * TM;         // [512][16] gemm1 out+partial0 / gemm3 partials
    float* P1 = A1 + NW * TM;         // [512][16] partial1 / gemm3 partials
    float* Y  = P1 + NW * TM;         // [256][16]
    float* KB = Y + DSTATE * TM;      // [6][256][16]

    const int tid = threadIdx.x;
    const int r0 = blockIdx.x * TM;
    float* BUg = g_BU + (size_t)blockIdx.x * (NW * TM);

    // N=512 gemms: 2-way k-split, 256 positions (2m x 128n)
    const int kh = tid >> 8;              // 0..1
    const int pos = tid & 255;
    const int m0 = (pos & 1) * 8;
    const int n0 = (pos >> 1) * 4;        // 128 n-blocks of 4
    // gemm3 (N=256): 4-way k-split, 128 positions (2m x 64n)
    const int q = tid >> 7;               // 0..3
    const int pos3 = tid & 127;
    const int m3 = (pos3 & 1) * 8;
    const int n3 = (pos3 >> 1) * 4;       // 64 n-blocks of 4

    // init Y; u into A0 rows 0-255 (k-major) for BU precompute
    for (int idx = tid; idx < TM * DSTATE; idx += NTH) {
        int m = idx >> 8, c = idx & 255;
        int r = r0 + m, traj = r & 1023;
        Y[c * TM + m] = x0[traj * DSTATE + c];
        A0[c * TM + m] = (r < 1024) ? uf[traj * DSTATE + c] : 0.f;
    }
    __syncthreads();

    // ---- BU = b1 + W1[:,256:512] @ u  (K=256, 2-way split) ----
    {
        u64 acc[16];
        zero16(acc);
        mma8x4(A0 + kh * 128 * TM + m0,
               g_W1T + (size_t)(DSTATE + kh * 128) * NW + n0, NW, 128, acc);
        store_partial4(kh ? P1 : A1, n0, m0, acc);
        __syncthreads();
        for (int i4 = tid; i4 < (NW * TM) / 4; i4 += NTH) {
            float4 a = reinterpret_cast<const float4*>(A1)[i4];
            float4 p = reinterpret_cast<const float4*>(P1)[i4];
            float bb = b1[i4 >> 2];
            reinterpret_cast<float4*>(BUg)[i4] =
                make_float4(a.x + p.x + bb, a.y + p.y + bb, a.z + p.z + bb, a.w + p.w + bb);
        }
        __syncthreads();
    }

    const float H = 1.0f / 60.0f;

    #pragma unroll 1
    for (int step = 0; step < NSTEPS; ++step) {
        #pragma unroll 1
        for (int s = 0; s < 6; ++s) {
            // build z = y + H * sum_j a_sj k_j -> A0 rows [0,256)
            for (int i4 = tid; i4 < (DSTATE * TM) / 4; i4 += NTH) {
                float4 y = reinterpret_cast<const float4*>(Y)[i4];
                float4 a = make_float4(0.f, 0.f, 0.f, 0.f);
                for (int j = 0; j < s; ++j) {
                    float4 kv = reinterpret_cast<const float4*>(KB + j * DSTATE * TM)[i4];
                    float aj = c_A[s][j];
                    a.x += aj * kv.x; a.y += aj * kv.y;
                    a.z += aj * kv.z; a.w += aj * kv.w;
                }
                y.x += H * a.x; y.y += H * a.y; y.z += H * a.z; y.w += H * a.w;
                reinterpret_cast<float4*>(A0)[i4] = y;
            }
            __syncthreads();

            // gemm1: A1 = relu(BU + W1[:, :256] @ z), K=256, 2-way split
            {
                u64 acc[16];
                zero16(acc);
                mma8x4(A0 + kh * 128 * TM + m0,
                       g_W1T + (size_t)(kh * 128) * NW + n0, NW, 128, acc);
                store_partial4(kh ? P1 : A1, n0, m0, acc);
                __syncthreads();
                for (int i4 = tid; i4 < (NW * TM) / 4; i4 += NTH) {
                    float4 a = reinterpret_cast<const float4*>(A1)[i4];
                    float4 p = reinterpret_cast<const float4*>(P1)[i4];
                    float4 bu = reinterpret_cast<const float4*>(BUg)[i4];
                    float4 v;
                    v.x = fmaxf(a.x + p.x + bu.x, 0.f);
                    v.y = fmaxf(a.y + p.y + bu.y, 0.f);
                    v.z = fmaxf(a.z + p.z + bu.z, 0.f);
                    v.w = fmaxf(a.w + p.w + bu.w, 0.f);
                    reinterpret_cast<float4*>(A1)[i4] = v;
                }
                __syncthreads();
            }
            // gemm2: A0 = relu(b2 + W2 @ h1), K=512, 2-way split
            {
                u64 acc[16];
                zero16(acc);
                mma8x4(A1 + kh * 256 * TM + m0,
                       g_W2T + (size_t)(kh * 256) * NW + n0, NW, 256, acc);
                store_partial4(kh ? P1 : A0, n0, m0, acc);
                __syncthreads();
                for (int i4 = tid; i4 < (NW * TM) / 4; i4 += NTH) {
                    float4 a = reinterpret_cast<const float4*>(A0)[i4];
                    float4 p = reinterpret_cast<const float4*>(P1)[i4];
                    float bb = b2[i4 >> 2];
                    float4 v;
                    v.x = fmaxf(a.x + p.x + bb, 0.f);
                    v.y = fmaxf(a.y + p.y + bb, 0.f);
                    v.z = fmaxf(a.z + p.z + bb, 0.f);
                    v.w = fmaxf(a.w + p.w + bb, 0.f);
                    reinterpret_cast<float4*>(A0)[i4] = v;
                }
                __syncthreads();
            }
            // gemm3: k_s = b3 + W3 @ h2, K=512, N=256, 4-way split
            // partials: q=0 -> A1 lo, q=1 -> A1 hi, q=2 -> P1 lo, q=3 -> P1 hi
            {
                u64 acc[16];
                zero16(acc);
                mma8x4(A0 + q * 128 * TM + m3,
                       g_W3T + (size_t)(q * 128) * DSTATE + n3, DSTATE, 128, acc);
                float* pdst = ((q & 2) ? P1 : A1) + (q & 1) * (DSTATE * TM);
                store_partial4(pdst, n3, m3, acc);
                __syncthreads();
                float* KBs = KB + s * DSTATE * TM;
                for (int i4 = tid; i4 < (DSTATE * TM) / 4; i4 += NTH) {
                    float4 p0 = reinterpret_cast<const float4*>(A1)[i4];
                    float4 p1 = reinterpret_cast<const float4*>(A1 + DSTATE * TM)[i4];
                    float4 p2 = reinterpret_cast<const float4*>(P1)[i4];
                    float4 p3 = reinterpret_cast<const float4*>(P1 + DSTATE * TM)[i4];
                    float bb = b3[i4 >> 2];
                    float4 v;
                    v.x = p0.x + p1.x + p2.x + p3.x + bb;
                    v.y = p0.y + p1.y + p2.y + p3.y + bb;
                    v.z = p0.z + p1.z + p2.z + p3.z + bb;
                    v.w = p0.w + p1.w + p2.w + p3.w + bb;
                    reinterpret_cast<float4*>(KBs)[i4] = v;
                }
                __syncthreads();
            }
        }
        // y += H * sum_i b_i k_i
        for (int i4 = tid; i4 < (DSTATE * TM) / 4; i4 += NTH) {
            float4 y = reinterpret_cast<const float4*>(Y)[i4];
            float4 a = make_float4(0.f, 0.f, 0.f, 0.f);
            #pragma unroll
            for (int j = 0; j < 6; ++j) {
                float4 kv = reinterpret_cast<const float4*>(KB + j * DSTATE * TM)[i4];
                float bj = c_Bw[j];
                a.x += bj * kv.x; a.y += bj * kv.y;
                a.z += bj * kv.z; a.w += bj * kv.w;
            }
            y.x += H * a.x; y.y += H * a.y; y.z += H * a.z; y.w += H * a.w;
            reinterpret_cast<float4*>(Y)[i4] = y;
        }
        __syncthreads();
    }

    for (int idx = tid; idx < TM * DSTATE; idx += NTH) {
        int m = idx >> 8, c = idx & 255;
        out[(size_t)(r0 + m) * DSTATE + c] = Y[c * TM + m];
    }
}

// ---------------- launch ----------------
extern "C" void kernel_launch(void* const* d_in, const int* in_sizes, int n_in,
                              void* d_out, int out_size) {
    (void)in_sizes; (void)n_in; (void)out_size;
    const float* x0 = (const float*)d_in[0];
    const float* uf = (const float*)d_in[1];
    const float* W1 = (const float*)d_in[2];
    const float* b1 = (const float*)d_in[3];
    const float* W2 = (const float*)d_in[4];
    const float* b2 = (const float*)d_in[5];
    const float* W3 = (const float*)d_in[6];
    const float* b3 = (const float*)d_in[7];
    float* out = (float*)d_out;

    dim3 tthreads(32, 8);
    transpose_kernel<<<dim3(DIN / 32, NW / 32), tthreads>>>(0, W1, NW, DIN);
    transpose_kernel<<<dim3(NW / 32, NW / 32), tthreads>>>(1, W2, NW, NW);
    transpose_kernel<<<dim3(NW / 32, DSTATE / 32), tthreads>>>(2, W3, DSTATE, NW);

    size_t smem_bytes = (size_t)(3 * NW * TM + 7 * DSTATE * TM) * sizeof(float);
    cudaFuncSetAttribute(ode_main, cudaFuncAttributeMaxDynamicSharedMemorySize, (int)smem_bytes);
    ode_main<<<NBLOCKS, NTH, smem_bytes>>>(x0, uf, b1, b2, b3, out);
}